// round 9
// baseline (speedup 1.0000x reference)
#include <cuda_runtime.h>

// GRU sequence encoder, round 9.
// N=16384, L=512, ES=32, HS=64, gates [r|z|n] (torch order).
//
// P[v][g] = emb[v].w_ih[g] + b_ih[g] precomputed (32000x192, L2-resident).
// Counting sort by length (desc), 16 seqs per CTA group.
// NT=384 (12 warps): warp w covers gate rows [16w,16w+16) x 2 seqs per pass
// (lane parity = seq). Each thread owns ONE gate row (64 weight regs) and
// serves its parity's 8 seqs. Each h LDS.128 now feeds two distinct seqs
// (padded h stride -> conflict-free) instead of a pure broadcast:
// ~4x fewer h-read wavefronts per seq-step.

#define N_SEQ   16384
#define L_SEQ   512
#define ES_DIM  32
#define HS_DIM  64
#define G3      192
#define WG      16
#define NGROUP  (N_SEQ / WG)   // 1024
#define NBUCKET 513
#define VOCAB   32000
#define NT      384
#define HPAD    17             // float4 stride of an h row (bank-decorrelated)

__device__ float P[VOCAB * G3];
__device__ int d_len[N_SEQ];
__device__ int d_bucket[NBUCKET];
__device__ int d_off[NBUCKET];
__device__ int d_sorted[N_SEQ];
__device__ int g_ctr;

#define FFMA2(acc, a, b) \
    asm("fma.rn.f32x2 %0, %1, %2, %0;" : "+l"(acc) : "l"(a), "l"(b))

__device__ __forceinline__ float pairsum2(unsigned long long u,
                                          unsigned long long v) {
    float ux = __uint_as_float((unsigned)u);
    float uy = __uint_as_float((unsigned)(u >> 32));
    float vx = __uint_as_float((unsigned)v);
    float vy = __uint_as_float((unsigned)(v >> 32));
    return (ux + uy) + (vx + vy);
}

// ---------------- prepass ----------------

__global__ void zero_kernel() {
    int t = threadIdx.x;
    if (t < NBUCKET) d_bucket[t] = 0;
    if (t == NBUCKET) g_ctr = 0;
}

#define LEN_CTAS 2048
#define P_ROWS_PER_CTA 64

__global__ void len_pre_kernel(const int* __restrict__ x,
                               const float* __restrict__ emb,
                               const float* __restrict__ w_ih,
                               const float* __restrict__ b_ih)
{
    if (blockIdx.x < LEN_CTAS) {
        int seq  = blockIdx.x * 8 + (threadIdx.x >> 5);
        int lane = threadIdx.x & 31;
        const int4* row = reinterpret_cast<const int4*>(x + (long)seq * L_SEQ);
        int c = 0;
        #pragma unroll
        for (int k = 0; k < 4; k++) {
            int4 v = row[lane + 32 * k];
            c += (v.x != 0) + (v.y != 0) + (v.z != 0) + (v.w != 0);
        }
        #pragma unroll
        for (int off = 16; off > 0; off >>= 1) c += __shfl_xor_sync(~0u, c, off);
        if (lane == 0) {
            d_len[seq] = c;
            atomicAdd(&d_bucket[c], 1);
        }
    } else {
        int j = threadIdx.x;
        if (j >= G3) return;
        float w[ES_DIM];
        {
            const float4* wr = reinterpret_cast<const float4*>(w_ih + (long)j * ES_DIM);
            #pragma unroll
            for (int k = 0; k < ES_DIM / 4; k++) {
                float4 v = wr[k];
                w[4*k+0] = v.x; w[4*k+1] = v.y; w[4*k+2] = v.z; w[4*k+3] = v.w;
            }
        }
        const float bj = b_ih[j];
        int v0 = (blockIdx.x - LEN_CTAS) * P_ROWS_PER_CTA;
        for (int v = v0; v < v0 + P_ROWS_PER_CTA && v < VOCAB; v++) {
            const float4* er = reinterpret_cast<const float4*>(emb + (long)v * ES_DIM);
            float acc = bj;
            #pragma unroll
            for (int k = 0; k < ES_DIM / 4; k++) {
                float4 e = __ldg(&er[k]);
                acc = fmaf(w[4*k+0], e.x, acc);
                acc = fmaf(w[4*k+1], e.y, acc);
                acc = fmaf(w[4*k+2], e.z, acc);
                acc = fmaf(w[4*k+3], e.w, acc);
            }
            P[(long)v * G3 + j] = acc;
        }
    }
}

__global__ void scan_scatter_kernel() {
    __shared__ int sb[NBUCKET], so[NBUCKET];
    int t = threadIdx.x;
    for (int i = t; i < NBUCKET; i += blockDim.x) sb[i] = d_bucket[i];
    __syncthreads();
    if (t == 0) {
        int run = 0;
        for (int l = NBUCKET - 1; l >= 0; l--) { so[l] = run; run += sb[l]; }
    }
    __syncthreads();
    for (int i = t; i < NBUCKET; i += blockDim.x) d_off[i] = so[i];
    __syncthreads();
    for (int seq = t; seq < N_SEQ; seq += blockDim.x) {
        int l = d_len[seq];
        int pos = atomicAdd(&d_off[l], 1);
        d_sorted[pos] = seq;
    }
}

// ---------------- main ----------------

__launch_bounds__(NT, 1)
__global__ void gru_main(const int*   __restrict__ x,
                         const float* __restrict__ w_hh,
                         const float* __restrict__ b_hh,
                         float*       __restrict__ out)
{
    __shared__ float  gx[2][WG][G3];        // 24 KB (dbl-buffered P rows)
    __shared__ float  gate[3][WG][HS_DIM];  // 12 KB
    __shared__ float4 h4[WG][HPAD];         // 4.25 KB (padded rows)
    __shared__ int    seq_sm[WG], len_sm[WG], gid_sm;

    const int tid = threadIdx.x;
    const int w   = tid >> 5;
    const int l   = tid & 31;
    const int j   = w * 16 + (l >> 1);      // gate row owned by this thread
    const int par = l & 1;                  // parity: which seqs this thread serves
    const int i   = j & 63;
    const int gsel = j >> 6;

    // one recurrent weight row in registers (64-bit packed pairs)
    ulonglong2 whh[HS_DIM / 4];
    {
        const ulonglong2* wp = reinterpret_cast<const ulonglong2*>(w_hh + (long)j * HS_DIM);
        #pragma unroll
        for (int k = 0; k < HS_DIM / 4; k++) whh[k] = wp[k];
    }
    const float bhh = b_hh[j];

    while (true) {
        if (tid == 0) gid_sm = atomicAdd(&g_ctr, 1);
        __syncthreads();
        const int g = gid_sm;
        if (g >= NGROUP) break;

        if (tid < WG) {
            int s = d_sorted[g * WG + tid];
            seq_sm[tid] = s;
            len_sm[tid] = d_len[s];
        }
        // zero h (including pad)
        if (tid < WG * HPAD) {
            reinterpret_cast<float4*>(h4)[tid] = make_float4(0.f, 0.f, 0.f, 0.f);
        }
        __syncthreads();

        const int maxlen = len_sm[0];
        int xoff[WG / 2];                   // this thread's 8 seqs (parity)
        #pragma unroll
        for (int m = 0; m < WG / 2; m++) xoff[m] = seq_sm[2 * m + par] * L_SEQ;

        if (maxlen > 0) {
            // prologue: gather gx(0) for own seqs
            #pragma unroll
            for (int m = 0; m < WG / 2; m++) {
                int tok = __ldg(&x[xoff[m]]);
                gx[0][2 * m + par][j] = __ldg(&P[(long)tok * G3 + j]);
            }
            __syncthreads();

            int p = 0;
            for (int t = 0; t < maxlen; t++) {
                const int tn = (t + 1 < L_SEQ) ? t + 1 : L_SEQ - 1;

                // matvec over own 8 seqs + prefetch gx(t+1) -> idle buffer
                #pragma unroll
                for (int m = 0; m < WG / 2; m++) {
                    const int s = 2 * m + par;
                    int tok = __ldg(&x[xoff[m] + tn]);
                    float pre = __ldg(&P[(long)tok * G3 + j]);

                    unsigned long long a0 = 0ull, a1 = 0ull;
                    const ulonglong2* hp =
                        reinterpret_cast<const ulonglong2*>(&h4[s][0]);
                    #pragma unroll
                    for (int k = 0; k < HS_DIM / 4; k++) {
                        ulonglong2 hv = hp[k];
                        FFMA2(a0, whh[k].x, hv.x);
                        FFMA2(a1, whh[k].y, hv.y);
                    }
                    gate[gsel][s][i] = pairsum2(a0, a1) + bhh;
                    gx[1 - p][s][j] = pre;
                }
                __syncthreads();   // gates + gx(t+1) ready; h reads done

                // update: 512 element-pairs over 384 threads (float2)
                #pragma unroll
                for (int q = 0; q < 2; q++) {
                    int u = tid + NT * q;
                    if (u < WG * HS_DIM / 2) {
                        int s = u >> 5, ii = (u & 31) * 2;
                        float2 gxr = *reinterpret_cast<const float2*>(&gx[p][s][ii]);
                        float2 gxz = *reinterpret_cast<const float2*>(&gx[p][s][64 + ii]);
                        float2 gxn = *reinterpret_cast<const float2*>(&gx[p][s][128 + ii]);
                        float2 ghr = *reinterpret_cast<const float2*>(&gate[0][s][ii]);
                        float2 ghz = *reinterpret_cast<const float2*>(&gate[1][s][ii]);
                        float2 ghn = *reinterpret_cast<const float2*>(&gate[2][s][ii]);
                        float* hp = reinterpret_cast<float*>(&h4[s][0]) + ii;
                        float2 ho = *reinterpret_cast<const float2*>(hp);
                        bool live = (t < len_sm[s]);

                        float rx = __fdividef(1.0f, 1.0f + __expf(-(gxr.x + ghr.x)));
                        float ry = __fdividef(1.0f, 1.0f + __expf(-(gxr.y + ghr.y)));
                        float zx = __fdividef(1.0f, 1.0f + __expf(-(gxz.x + ghz.x)));
                        float zy = __fdividef(1.0f, 1.0f + __expf(-(gxz.y + ghz.y)));
                        float ax = fmaf(rx, ghn.x, gxn.x);
                        float ay = fmaf(ry, ghn.y, gxn.y);
                        float nx = 1.0f - __fdividef(2.0f, __expf(2.0f * ax) + 1.0f);
                        float ny = 1.0f - __fdividef(2.0f, __expf(2.0f * ay) + 1.0f);
                        float2 hn;
                        hn.x = live ? fmaf(zx, ho.x - nx, nx) : ho.x;
                        hn.y = live ? fmaf(zy, ho.y - ny, ny) : ho.y;
                        *reinterpret_cast<float2*>(hp) = hn;
                    }
                }
                __syncthreads();   // h published
                p ^= 1;
            }
        } else {
            __syncthreads();
        }

        // outputs: 512 float2 over 384 threads
        #pragma unroll
        for (int q = 0; q < 2; q++) {
            int u = tid + NT * q;
            if (u < WG * HS_DIM / 2) {
                int s = u >> 5, ii = (u & 31) * 2;
                *reinterpret_cast<float2*>(&out[(long)seq_sm[s] * HS_DIM + ii]) =
                    *reinterpret_cast<const float2*>(
                        reinterpret_cast<const float*>(&h4[s][0]) + ii);
            }
        }
        // next claim barrier orders smem reuse
    }
}

extern "C" void kernel_launch(void* const* d_in, const int* in_sizes, int n_in,
                              void* d_out, int out_size)
{
    const int*   x    = (const int*)  d_in[0];
    const float* emb  = (const float*)d_in[1];
    const float* w_ih = (const float*)d_in[2];
    const float* w_hh = (const float*)d_in[3];
    const float* b_ih = (const float*)d_in[4];
    const float* b_hh = (const float*)d_in[5];
    float*       out  = (float*)d_out;

    zero_kernel<<<1, 1024>>>();
    len_pre_kernel<<<LEN_CTAS + (VOCAB + P_ROWS_PER_CTA - 1) / P_ROWS_PER_CTA, 256>>>(
        x, emb, w_ih, b_ih);
    scan_scatter_kernel<<<1, 256>>>();
    gru_main<<<148, NT>>>(x, w_hh, b_hh, out);
}

// round 10
// speedup vs baseline: 1.4457x; 1.4457x over previous
#include <cuda_runtime.h>

// GRU sequence encoder, round 10 = R8 frame + k-split lane pairing.
// N=16384, L=512, ES=32, HS=64, gates [r|z|n] (torch order).
//
// Matvec: warp w covers gate rows [32w, 32w+32). Lane l handles rows
// rowA=(32w+(l&15)) and rowB=rowA+16, k-half kh=(l>>4): 64 weight regs,
// each h LDS.128 feeds 4 FFMA2, partials combined via shfl_down(16).
// h stored k-interleaved so the two half-warp addresses are 16B apart
// (conflict-free). 192 threads, 2 CTAs/SM, WG=16 length-sorted seqs.

#define N_SEQ   16384
#define L_SEQ   512
#define ES_DIM  32
#define HS_DIM  64
#define G3      192
#define WG      16
#define NGROUP  (N_SEQ / WG)   // 1024
#define NBUCKET 513
#define VOCAB   32000
#define NT      192

__device__ float P[VOCAB * G3];
__device__ int d_len[N_SEQ];
__device__ int d_bucket[NBUCKET];
__device__ int d_off[NBUCKET];
__device__ int d_sorted[N_SEQ];
__device__ int g_ctr;

#define FFMA2(acc, a, b) \
    asm("fma.rn.f32x2 %0, %1, %2, %0;" : "+l"(acc) : "l"(a), "l"(b))

__device__ __forceinline__ float pairsum2(unsigned long long u,
                                          unsigned long long v) {
    float ux = __uint_as_float((unsigned)u);
    float uy = __uint_as_float((unsigned)(u >> 32));
    float vx = __uint_as_float((unsigned)v);
    float vy = __uint_as_float((unsigned)(v >> 32));
    return (ux + uy) + (vx + vy);
}

// permuted h layout: stored float4 chunk index for logical chunk c (0..15):
// pairs (k, k+8) adjacent -> logical c maps to 2*(c&7) + (c>>3)
__device__ __forceinline__ int hperm(int c) { return 2 * (c & 7) + (c >> 3); }

// ---------------- prepass ----------------

__global__ void zero_kernel() {
    int t = threadIdx.x;
    if (t < NBUCKET) d_bucket[t] = 0;
    if (t == NBUCKET) g_ctr = 0;
}

#define LEN_CTAS 2048
#define P_ROWS_PER_CTA 64

__global__ void len_pre_kernel(const int* __restrict__ x,
                               const float* __restrict__ emb,
                               const float* __restrict__ w_ih,
                               const float* __restrict__ b_ih)
{
    if (blockIdx.x < LEN_CTAS) {
        int seq  = blockIdx.x * 8 + (threadIdx.x >> 5);
        int lane = threadIdx.x & 31;
        const int4* row = reinterpret_cast<const int4*>(x + (long)seq * L_SEQ);
        int c = 0;
        #pragma unroll
        for (int k = 0; k < 4; k++) {
            int4 v = row[lane + 32 * k];
            c += (v.x != 0) + (v.y != 0) + (v.z != 0) + (v.w != 0);
        }
        #pragma unroll
        for (int off = 16; off > 0; off >>= 1) c += __shfl_xor_sync(~0u, c, off);
        if (lane == 0) {
            d_len[seq] = c;
            atomicAdd(&d_bucket[c], 1);
        }
    } else {
        int j = threadIdx.x;
        if (j >= G3) return;
        float w[ES_DIM];
        {
            const float4* wr = reinterpret_cast<const float4*>(w_ih + (long)j * ES_DIM);
            #pragma unroll
            for (int k = 0; k < ES_DIM / 4; k++) {
                float4 v = wr[k];
                w[4*k+0] = v.x; w[4*k+1] = v.y; w[4*k+2] = v.z; w[4*k+3] = v.w;
            }
        }
        const float bj = b_ih[j];
        int v0 = (blockIdx.x - LEN_CTAS) * P_ROWS_PER_CTA;
        for (int v = v0; v < v0 + P_ROWS_PER_CTA && v < VOCAB; v++) {
            const float4* er = reinterpret_cast<const float4*>(emb + (long)v * ES_DIM);
            float acc = bj;
            #pragma unroll
            for (int k = 0; k < ES_DIM / 4; k++) {
                float4 e = __ldg(&er[k]);
                acc = fmaf(w[4*k+0], e.x, acc);
                acc = fmaf(w[4*k+1], e.y, acc);
                acc = fmaf(w[4*k+2], e.z, acc);
                acc = fmaf(w[4*k+3], e.w, acc);
            }
            P[(long)v * G3 + j] = acc;
        }
    }
}

__global__ void scan_scatter_kernel() {
    __shared__ int sb[NBUCKET], so[NBUCKET];
    int t = threadIdx.x;
    for (int i = t; i < NBUCKET; i += blockDim.x) sb[i] = d_bucket[i];
    __syncthreads();
    if (t == 0) {
        int run = 0;
        for (int l = NBUCKET - 1; l >= 0; l--) { so[l] = run; run += sb[l]; }
    }
    __syncthreads();
    for (int i = t; i < NBUCKET; i += blockDim.x) d_off[i] = so[i];
    __syncthreads();
    for (int seq = t; seq < N_SEQ; seq += blockDim.x) {
        int l = d_len[seq];
        int pos = atomicAdd(&d_off[l], 1);
        d_sorted[pos] = seq;
    }
}

// ---------------- main ----------------

__launch_bounds__(NT, 2)
__global__ void gru_main(const int*   __restrict__ x,
                         const float* __restrict__ w_hh,
                         const float* __restrict__ b_hh,
                         float*       __restrict__ out)
{
    __shared__ float  gx[2][WG][G3];        // 24 KB (dbl-buffered P rows)
    __shared__ float  gate[3][WG][HS_DIM];  // 12 KB
    __shared__ float4 hst[WG][16];          //  4 KB (k-interleaved h)
    __shared__ int    seq_sm[WG], len_sm[WG], gid_sm;

    const int tid = threadIdx.x;
    const int w   = tid >> 5;
    const int l   = tid & 31;
    const int kh  = l >> 4;                 // k-half: 0 -> k[0:32), 1 -> k[32:64)
    const int lr  = l & 15;
    const int rowA = w * 32 + lr;
    const int rowB = rowA + 16;
    const int gsA = rowA >> 6, iA = rowA & 63;
    const int gsB = rowB >> 6, iB = rowB & 63;

    // half-rows of two weight rows (8 ulonglong2 each = 64 float regs total)
    ulonglong2 wA[8], wB[8];
    {
        const ulonglong2* pA =
            reinterpret_cast<const ulonglong2*>(w_hh + (long)rowA * HS_DIM + kh * 32);
        const ulonglong2* pB =
            reinterpret_cast<const ulonglong2*>(w_hh + (long)rowB * HS_DIM + kh * 32);
        #pragma unroll
        for (int k = 0; k < 8; k++) { wA[k] = pA[k]; wB[k] = pB[k]; }
    }
    const float bhA = b_hh[rowA];
    const float bhB = b_hh[rowB];

    while (true) {
        if (tid == 0) gid_sm = atomicAdd(&g_ctr, 1);
        __syncthreads();
        const int g = gid_sm;
        if (g >= NGROUP) break;

        if (tid < WG) {
            int s = d_sorted[g * WG + tid];
            seq_sm[tid] = s;
            len_sm[tid] = d_len[s];
        }
        for (int u = tid; u < WG * 16; u += NT) {
            reinterpret_cast<float4*>(hst)[u] = make_float4(0.f, 0.f, 0.f, 0.f);
        }
        __syncthreads();

        const int maxlen = len_sm[0];
        int xoff[WG];
        #pragma unroll
        for (int s = 0; s < WG; s++) xoff[s] = seq_sm[s] * L_SEQ;

        if (maxlen > 0) {
            // prologue: gather gx(0) (thread tid fetches column tid)
            #pragma unroll
            for (int s = 0; s < WG; s++) {
                int tok = __ldg(&x[xoff[s]]);
                gx[0][s][tid] = __ldg(&P[(long)tok * G3 + tid]);
            }
            __syncthreads();

            int p = 0;
            for (int t = 0; t < maxlen; t++) {
                const int tn = (t + 1 < L_SEQ) ? t + 1 : L_SEQ - 1;

                // matvec + prefetch gx(t+1) -> idle buffer
                #pragma unroll
                for (int s = 0; s < WG; s++) {
                    int tok = __ldg(&x[xoff[s] + tn]);
                    float pre = __ldg(&P[(long)tok * G3 + tid]);

                    unsigned long long a0 = 0ull, a1 = 0ull;
                    unsigned long long b0 = 0ull, b1 = 0ull;
                    const ulonglong2* hp =
                        reinterpret_cast<const ulonglong2*>(&hst[s][0]);
                    #pragma unroll
                    for (int k = 0; k < 8; k++) {
                        ulonglong2 hv = hp[2 * k + kh];   // interleaved layout
                        FFMA2(a0, wA[k].x, hv.x);
                        FFMA2(a1, wA[k].y, hv.y);
                        FFMA2(b0, wB[k].x, hv.x);
                        FFMA2(b1, wB[k].y, hv.y);
                    }
                    float sA = pairsum2(a0, a1);
                    float sB = pairsum2(b0, b1);
                    sA += __shfl_down_sync(0xffffffffu, sA, 16);
                    sB += __shfl_down_sync(0xffffffffu, sB, 16);
                    if (l < 16) {
                        gate[gsA][s][iA] = sA + bhA;
                        gate[gsB][s][iB] = sB + bhB;
                    }
                    gx[1 - p][s][tid] = pre;
                }
                __syncthreads();   // gates + gx(t+1) ready; h reads done

                // update: 512 element-pairs over 192 threads (float2),
                // h accessed through the interleaved layout
                #pragma unroll
                for (int q = 0; q < (WG * HS_DIM / 2 + NT - 1) / NT; q++) {
                    int u = tid + NT * q;
                    if (u < WG * HS_DIM / 2) {
                        int s = u >> 5, ii = (u & 31) * 2;
                        float2 gxr = *reinterpret_cast<const float2*>(&gx[p][s][ii]);
                        float2 gxz = *reinterpret_cast<const float2*>(&gx[p][s][64 + ii]);
                        float2 gxn = *reinterpret_cast<const float2*>(&gx[p][s][128 + ii]);
                        float2 ghr = *reinterpret_cast<const float2*>(&gate[0][s][ii]);
                        float2 ghz = *reinterpret_cast<const float2*>(&gate[1][s][ii]);
                        float2 ghn = *reinterpret_cast<const float2*>(&gate[2][s][ii]);
                        float* hp = reinterpret_cast<float*>(&hst[s][hperm(ii >> 2)])
                                    + (ii & 3);
                        float2 ho = *reinterpret_cast<const float2*>(hp);
                        bool live = (t < len_sm[s]);

                        float rx = __fdividef(1.0f, 1.0f + __expf(-(gxr.x + ghr.x)));
                        float ry = __fdividef(1.0f, 1.0f + __expf(-(gxr.y + ghr.y)));
                        float zx = __fdividef(1.0f, 1.0f + __expf(-(gxz.x + ghz.x)));
                        float zy = __fdividef(1.0f, 1.0f + __expf(-(gxz.y + ghz.y)));
                        float ax = fmaf(rx, ghn.x, gxn.x);
                        float ay = fmaf(ry, ghn.y, gxn.y);
                        float nx = 1.0f - __fdividef(2.0f, __expf(2.0f * ax) + 1.0f);
                        float ny = 1.0f - __fdividef(2.0f, __expf(2.0f * ay) + 1.0f);
                        float2 hn;
                        hn.x = live ? fmaf(zx, ho.x - nx, nx) : ho.x;
                        hn.y = live ? fmaf(zy, ho.y - ny, ny) : ho.y;
                        *reinterpret_cast<float2*>(hp) = hn;
                    }
                }
                __syncthreads();   // h published
                p ^= 1;
            }
        } else {
            __syncthreads();
        }

        // outputs: 512 float2 over 192 threads (de-permute h)
        for (int u = tid; u < WG * HS_DIM / 2; u += NT) {
            int s = u >> 5, ii = (u & 31) * 2;
            const float* hp = reinterpret_cast<const float*>(&hst[s][hperm(ii >> 2)])
                              + (ii & 3);
            *reinterpret_cast<float2*>(&out[(long)seq_sm[s] * HS_DIM + ii]) =
                *reinterpret_cast<const float2*>(hp);
        }
        // next claim barrier orders smem reuse
    }
}

extern "C" void kernel_launch(void* const* d_in, const int* in_sizes, int n_in,
                              void* d_out, int out_size)
{
    const int*   x    = (const int*)  d_in[0];
    const float* emb  = (const float*)d_in[1];
    const float* w_ih = (const float*)d_in[2];
    const float* w_hh = (const float*)d_in[3];
    const float* b_ih = (const float*)d_in[4];
    const float* b_hh = (const float*)d_in[5];
    float*       out  = (float*)d_out;

    zero_kernel<<<1, 1024>>>();
    len_pre_kernel<<<LEN_CTAS + (VOCAB + P_ROWS_PER_CTA - 1) / P_ROWS_PER_CTA, 256>>>(
        x, emb, w_ih, b_ih);
    scan_scatter_kernel<<<1, 256>>>();
    gru_main<<<296, NT>>>(x, w_hh, b_hh, out);
}

// round 13
// speedup vs baseline: 1.5985x; 1.1057x over previous
#include <cuda_runtime.h>
#include <cuda_bf16.h>
#include <cstdint>

// GRU sequence encoder, round 12: mma.sync (HMMA) tensor-core recurrence.
// (tcgen05 unavailable: harness compiles PTX for sm_103 base target.)
// N=16384, L=512, ES=32, HS=64, gates [r|z|n] (torch order).
//
// Warp-independent: each warp owns 16 length-sorted seqs; per step
// gh[16,192] = h@w_hh^T via 288 mma.m16n8k16 (bf16 split precision,
// 3 terms). A(h) fragments live in registers (C-frag -> A-frag repack);
// B(w) in SMEM via conflict-free ldmatrix. No __syncthreads in the loop.

#define N_SEQ   16384
#define L_SEQ   512
#define ES_DIM  32
#define HS_DIM  64
#define G3      192
#define NGROUP  (N_SEQ / 16)   // 1024 groups of 16
#define NBUCKET 513
#define VOCAB   32000
#define WROW    72             // padded half-stride of w tiles (144 B rows)

__device__ float P[(size_t)VOCAB * G3];   // e.w_ih^T + b_ih (+b_hh for r,z)
__device__ int d_len[N_SEQ];
__device__ int d_bucket[NBUCKET];
__device__ int d_off[NBUCKET];
__device__ int d_sorted[N_SEQ];

// ---------------- PTX helpers ----------------

__device__ __forceinline__ uint32_t smem_to_u32(const void* p) {
    uint32_t a;
    asm("{ .reg .u64 t; cvta.to.shared.u64 t, %1; cvt.u32.u64 %0, t; }"
        : "=r"(a) : "l"(p));
    return a;
}

#define LDSM_X2(r, addr) \
    asm volatile("ldmatrix.sync.aligned.m8n8.x2.shared.b16 {%0,%1}, [%2];" \
                 : "=r"((r)[0]), "=r"((r)[1]) : "r"(addr))

#define MMA_BF16(c, a, b) \
    asm volatile("mma.sync.aligned.m16n8k16.row.col.f32.bf16.bf16.f32 " \
                 "{%0,%1,%2,%3}, {%4,%5,%6,%7}, {%8,%9}, {%0,%1,%2,%3};" \
                 : "+f"((c)[0]), "+f"((c)[1]), "+f"((c)[2]), "+f"((c)[3]) \
                 : "r"((a)[0]), "r"((a)[1]), "r"((a)[2]), "r"((a)[3]), \
                   "r"((b)[0]), "r"((b)[1]))

// one n-tile (8 gate rows): 12 HMMA with shared B_hi
__device__ __forceinline__ void mma_ntile(float acc[4],
                                          uint32_t addr_hi, uint32_t addr_lo,
                                          const uint32_t Ahi[4][4],
                                          const uint32_t Alo[4][4])
{
    uint32_t bh[4][2], bl[4][2];
    #pragma unroll
    for (int k = 0; k < 4; k++) {
        LDSM_X2(bh[k], addr_hi + 32 * k);
        LDSM_X2(bl[k], addr_lo + 32 * k);
    }
    #pragma unroll
    for (int k = 0; k < 4; k++) MMA_BF16(acc, Ahi[k], bh[k]);
    #pragma unroll
    for (int k = 0; k < 4; k++) MMA_BF16(acc, Alo[k], bh[k]);
    #pragma unroll
    for (int k = 0; k < 4; k++) MMA_BF16(acc, Ahi[k], bl[k]);
}

// ---------------- prepass ----------------

__global__ void zero_kernel() {
    int t = threadIdx.x;
    if (t < NBUCKET) d_bucket[t] = 0;
}

#define LEN_CTAS 2048
#define P_ROWS_PER_CTA 64

__global__ void len_pre_kernel(const int* __restrict__ x,
                               const float* __restrict__ emb,
                               const float* __restrict__ w_ih,
                               const float* __restrict__ b_ih,
                               const float* __restrict__ b_hh)
{
    if (blockIdx.x < LEN_CTAS) {
        int seq  = blockIdx.x * 8 + (threadIdx.x >> 5);
        int lane = threadIdx.x & 31;
        const int4* row = reinterpret_cast<const int4*>(x + (long)seq * L_SEQ);
        int c = 0;
        #pragma unroll
        for (int k = 0; k < 4; k++) {
            int4 v = row[lane + 32 * k];
            c += (v.x != 0) + (v.y != 0) + (v.z != 0) + (v.w != 0);
        }
        #pragma unroll
        for (int off = 16; off > 0; off >>= 1) c += __shfl_xor_sync(~0u, c, off);
        if (lane == 0) {
            d_len[seq] = c;
            atomicAdd(&d_bucket[c], 1);
        }
    } else {
        int j = threadIdx.x;
        if (j >= G3) return;
        float w[ES_DIM];
        {
            const float4* wr = reinterpret_cast<const float4*>(w_ih + (long)j * ES_DIM);
            #pragma unroll
            for (int k = 0; k < ES_DIM / 4; k++) {
                float4 v = wr[k];
                w[4*k+0] = v.x; w[4*k+1] = v.y; w[4*k+2] = v.z; w[4*k+3] = v.w;
            }
        }
        // fold b_ih always; fold b_hh for r,z gates (n-gate keeps b_hn separate)
        const float bj = b_ih[j] + ((j < 128) ? b_hh[j] : 0.0f);
        int v0 = (blockIdx.x - LEN_CTAS) * P_ROWS_PER_CTA;
        for (int v = v0; v < v0 + P_ROWS_PER_CTA && v < VOCAB; v++) {
            const float4* er = reinterpret_cast<const float4*>(emb + (long)v * ES_DIM);
            float acc = bj;
            #pragma unroll
            for (int k = 0; k < ES_DIM / 4; k++) {
                float4 e = __ldg(&er[k]);
                acc = fmaf(w[4*k+0], e.x, acc);
                acc = fmaf(w[4*k+1], e.y, acc);
                acc = fmaf(w[4*k+2], e.z, acc);
                acc = fmaf(w[4*k+3], e.w, acc);
            }
            P[(size_t)v * G3 + j] = acc;
        }
    }
}

__global__ void scan_scatter_kernel() {
    __shared__ int sb[NBUCKET], so[NBUCKET];
    int t = threadIdx.x;
    for (int i = t; i < NBUCKET; i += blockDim.x) sb[i] = d_bucket[i];
    __syncthreads();
    if (t == 0) {
        int run = 0;
        for (int l = NBUCKET - 1; l >= 0; l--) { so[l] = run; run += sb[l]; }
    }
    __syncthreads();
    for (int i = t; i < NBUCKET; i += blockDim.x) d_off[i] = so[i];
    __syncthreads();
    for (int seq = t; seq < N_SEQ; seq += blockDim.x) {
        int l = d_len[seq];
        int pos = atomicAdd(&d_off[l], 1);
        d_sorted[pos] = seq;
    }
}

// ---------------- main: HMMA recurrence ----------------

#define SMEM_SZ (2 * G3 * WROW * 2)   // w_hi + w_lo, bf16, 55296 B

__global__ void __launch_bounds__(256, 1)
gru_mma(const int* __restrict__ x, const float* __restrict__ w_hh,
        const float* __restrict__ b_hh, float* __restrict__ out)
{
    extern __shared__ __align__(16) char smem[];
    __nv_bfloat16* whi = reinterpret_cast<__nv_bfloat16*>(smem);
    __nv_bfloat16* wlo = whi + G3 * WROW;

    const int tid = threadIdx.x;

    // build split-precision B tiles (once per CTA)
    for (int idx = tid; idx < G3 * HS_DIM; idx += 256) {
        int r = idx >> 6, k = idx & 63;
        float w = w_hh[(long)r * HS_DIM + k];
        __nv_bfloat16 hi = __float2bfloat16(w);
        whi[r * WROW + k] = hi;
        wlo[r * WROW + k] = __float2bfloat16(w - __bfloat162float(hi));
    }
    __syncthreads();

    const int wid  = tid >> 5;
    const int lane = tid & 31;
    const int grp  = blockIdx.x * 8 + wid;
    if (grp >= NGROUP) return;

    const int g  = lane >> 2;    // row group: owns seqs g and g+8 of the 16
    const int t4 = lane & 3;     // column group: cols 2*t4, 2*t4+1 per 8-tile

    const int base = grp * 16;
    const int seqA = d_sorted[base + g];
    const int seqB = d_sorted[base + g + 8];
    const int lenA = d_len[seqA];
    const int lenB = d_len[seqB];
    const int maxlen = d_len[d_sorted[base]];   // descending sort

    // ldmatrix per-lane address component (x2: lanes 0-15 -> 16 rows)
    const uint32_t whi_u = smem_to_u32(whi);
    const uint32_t wlo_u = smem_to_u32(wlo);
    const uint32_t laddr = (uint32_t)((lane & 7) * (WROW * 2) + ((lane >> 3) & 1) * 16);

    // b_hn (n-gate recurrent bias) for this thread's 16 dims
    float bhn[16];
    #pragma unroll
    for (int d = 0; d < 8; d++) {
        float2 bb = __ldg(reinterpret_cast<const float2*>(b_hh + 128 + 8 * d + 2 * t4));
        bhn[2 * d]     = bb.x;
        bhn[2 * d + 1] = bb.y;
    }

    float hA[16], hB[16];
    uint32_t Ahi[4][4], Alo[4][4];
    #pragma unroll
    for (int i = 0; i < 16; i++) { hA[i] = 0.f; hB[i] = 0.f; }
    #pragma unroll
    for (int k = 0; k < 4; k++)
        #pragma unroll
        for (int i = 0; i < 4; i++) { Ahi[k][i] = 0u; Alo[k][i] = 0u; }

    const int* xA = x + (size_t)seqA * L_SEQ;
    const int* xB = x + (size_t)seqB * L_SEQ;
    int tokA = __ldg(xA);
    int tokB = __ldg(xB);

    for (int t = 0; t < maxlen; t++) {
        float accR[8][4], accZ[8][4], accN[8][4];
        #pragma unroll
        for (int d = 0; d < 8; d++)
            #pragma unroll
            for (int i = 0; i < 4; i++) { accR[d][i] = 0.f; accZ[d][i] = 0.f; accN[d][i] = 0.f; }

        // ---- MMA: 24 n-tiles x 12 HMMA ----
        #pragma unroll
        for (int d = 0; d < 8; d++) {
            uint32_t ro = (uint32_t)(8 * d) * (WROW * 2) + laddr;
            mma_ntile(accR[d], whi_u + ro, wlo_u + ro, Ahi, Alo);
        }
        #pragma unroll
        for (int d = 0; d < 8; d++) {
            uint32_t ro = (uint32_t)(64 + 8 * d) * (WROW * 2) + laddr;
            mma_ntile(accZ[d], whi_u + ro, wlo_u + ro, Ahi, Alo);
        }
        #pragma unroll
        for (int d = 0; d < 8; d++) {
            uint32_t ro = (uint32_t)(128 + 8 * d) * (WROW * 2) + laddr;
            mma_ntile(accN[d], whi_u + ro, wlo_u + ro, Ahi, Alo);
        }

        // prefetch next tokens
        const int tn = (t + 1 < L_SEQ) ? t + 1 : t;
        const int tokA_n = __ldg(xA + tn);
        const int tokB_n = __ldg(xB + tn);

        const float* pA = P + (size_t)tokA * G3;
        const float* pB = P + (size_t)tokB * G3;
        const bool liveA = (t < lenA);
        const bool liveB = (t < lenB);

        // ---- epilogue per dim-tile ----
        #pragma unroll
        for (int d = 0; d < 8; d++) {
            const int c0 = 8 * d + 2 * t4;
            float2 gxrA = __ldg(reinterpret_cast<const float2*>(pA + c0));
            float2 gxzA = __ldg(reinterpret_cast<const float2*>(pA + 64 + c0));
            float2 gxnA = __ldg(reinterpret_cast<const float2*>(pA + 128 + c0));
            float2 gxrB = __ldg(reinterpret_cast<const float2*>(pB + c0));
            float2 gxzB = __ldg(reinterpret_cast<const float2*>(pB + 64 + c0));
            float2 gxnB = __ldg(reinterpret_cast<const float2*>(pB + 128 + c0));

            #pragma unroll
            for (int i = 0; i < 2; i++) {
                // seq A (acc slots 0,1), seq B (acc slots 2,3)
                float prA = (i ? gxrA.y : gxrA.x) + accR[d][i];
                float pzA = (i ? gxzA.y : gxzA.x) + accZ[d][i];
                float xnA = (i ? gxnA.y : gxnA.x);
                float hnA = accN[d][i] + bhn[2 * d + i];
                float rA = __fdividef(1.0f, 1.0f + __expf(-prA));
                float zA = __fdividef(1.0f, 1.0f + __expf(-pzA));
                float aA = fmaf(rA, hnA, xnA);
                float nA = 1.0f - __fdividef(2.0f, __expf(2.0f * aA) + 1.0f);
                float hoA = hA[2 * d + i];
                hA[2 * d + i] = liveA ? fmaf(zA, hoA - nA, nA) : hoA;

                float prB = (i ? gxrB.y : gxrB.x) + accR[d][2 + i];
                float pzB = (i ? gxzB.y : gxzB.x) + accZ[d][2 + i];
                float xnB = (i ? gxnB.y : gxnB.x);
                float hnB = accN[d][2 + i] + bhn[2 * d + i];
                float rB = __fdividef(1.0f, 1.0f + __expf(-prB));
                float zB = __fdividef(1.0f, 1.0f + __expf(-pzB));
                float aB = fmaf(rB, hnB, xnB);
                float nB = 1.0f - __fdividef(2.0f, __expf(2.0f * aB) + 1.0f);
                float hoB = hB[2 * d + i];
                hB[2 * d + i] = liveB ? fmaf(zB, hoB - nB, nB) : hoB;
            }
        }
        tokA = tokA_n;
        tokB = tokB_n;

        // ---- repack h into next step's A fragments (pure registers) ----
        #pragma unroll
        for (int k = 0; k < 4; k++) {
            float a0l = hA[4 * k],     a0h = hA[4 * k + 1];
            float a1l = hB[4 * k],     a1h = hB[4 * k + 1];
            float a2l = hA[4 * k + 2], a2h = hA[4 * k + 3];
            float a3l = hB[4 * k + 2], a3h = hB[4 * k + 3];
            uint32_t p0, p1, p2, p3;
            asm("cvt.rn.bf16x2.f32 %0, %1, %2;" : "=r"(p0) : "f"(a0h), "f"(a0l));
            asm("cvt.rn.bf16x2.f32 %0, %1, %2;" : "=r"(p1) : "f"(a1h), "f"(a1l));
            asm("cvt.rn.bf16x2.f32 %0, %1, %2;" : "=r"(p2) : "f"(a2h), "f"(a2l));
            asm("cvt.rn.bf16x2.f32 %0, %1, %2;" : "=r"(p3) : "f"(a3h), "f"(a3l));
            Ahi[k][0] = p0; Ahi[k][1] = p1; Ahi[k][2] = p2; Ahi[k][3] = p3;
            float r0l = a0l - __uint_as_float(p0 << 16);
            float r0h = a0h - __uint_as_float(p0 & 0xffff0000u);
            float r1l = a1l - __uint_as_float(p1 << 16);
            float r1h = a1h - __uint_as_float(p1 & 0xffff0000u);
            float r2l = a2l - __uint_as_float(p2 << 16);
            float r2h = a2h - __uint_as_float(p2 & 0xffff0000u);
            float r3l = a3l - __uint_as_float(p3 << 16);
            float r3h = a3h - __uint_as_float(p3 & 0xffff0000u);
            asm("cvt.rn.bf16x2.f32 %0, %1, %2;" : "=r"(Alo[k][0]) : "f"(r0h), "f"(r0l));
            asm("cvt.rn.bf16x2.f32 %0, %1, %2;" : "=r"(Alo[k][1]) : "f"(r1h), "f"(r1l));
            asm("cvt.rn.bf16x2.f32 %0, %1, %2;" : "=r"(Alo[k][2]) : "f"(r2h), "f"(r2l));
            asm("cvt.rn.bf16x2.f32 %0, %1, %2;" : "=r"(Alo[k][3]) : "f"(r3h), "f"(r3l));
        }
    }

    // ---- output ----
    #pragma unroll
    for (int d = 0; d < 8; d++) {
        const int c0 = 8 * d + 2 * t4;
        *reinterpret_cast<float2*>(&out[(size_t)seqA * HS_DIM + c0]) =
            make_float2(hA[2 * d], hA[2 * d + 1]);
        *reinterpret_cast<float2*>(&out[(size_t)seqB * HS_DIM + c0]) =
            make_float2(hB[2 * d], hB[2 * d + 1]);
    }
}

extern "C" void kernel_launch(void* const* d_in, const int* in_sizes, int n_in,
                              void* d_out, int out_size)
{
    const int*   x    = (const int*)  d_in[0];
    const float* emb  = (const float*)d_in[1];
    const float* w_ih = (const float*)d_in[2];
    const float* w_hh = (const float*)d_in[3];
    const float* b_ih = (const float*)d_in[4];
    const float* b_hh = (const float*)d_in[5];
    float*       out  = (float*)d_out;

    cudaFuncSetAttribute(gru_mma, cudaFuncAttributeMaxDynamicSharedMemorySize, SMEM_SZ);

    zero_kernel<<<1, 1024>>>();
    len_pre_kernel<<<LEN_CTAS + (VOCAB + P_ROWS_PER_CTA - 1) / P_ROWS_PER_CTA, 256>>>(
        x, emb, w_ih, b_ih, b_hh);
    scan_scatter_kernel<<<1, 256>>>();
    gru_mma<<<NGROUP / 8, 256, SMEM_SZ>>>(x, w_hh, b_hh, out);
}